// round 12
// baseline (speedup 1.0000x reference)
#include <cuda_runtime.h>
#include <cuda_bf16.h>

// Problem constants (B=2, H=8, S=256, D=64)
#define BATCH 2
#define NHEAD 8
#define SEQ   256
#define DIM   64
#define NROWS (BATCH * NHEAD * SEQ)   // 4096

// Fused structure-attention kernel, 2 query rows per CTA (same head).
// 128 threads (4 warps), 8 CTAs/SM, 64 regs. grid = NROWS/2.
//
// key/val are loaded ONCE per CTA and applied to both rows -> L2 hit
// traffic halves. ks/vs streams are per-row (compulsory DRAM traffic).
//
// Warp lane split: sub = lane&15 owns d-range [4*sub,4*sub+4),
//                  half = lane>>4 selects one of 2 k-rows per iteration.
// Each warp owns 64 k-rows: k in [warp*64, warp*64+64).
__global__ __launch_bounds__(128, 8) void attn_struct_kernel(
    const float* __restrict__ q_,     // [B,H,S,D]
    const float* __restrict__ k_,     // [B,H,S,D]
    const float* __restrict__ v_,     // [B,H,S,D]
    const float* __restrict__ ks_,    // [B,H,S,S,D]
    const float* __restrict__ vs_,    // [B,H,S,S,D]
    const float* __restrict__ mask_,  // [B,S]
    float* __restrict__ out_,         // [B,H,S,D]
    float* __restrict__ attn_)        // [B,H,S,S]
{
    const int r0   = blockIdx.x * 2;     // even row; r1 = r0+1 same head
    const int r1   = r0 + 1;
    const int bh   = r0 >> 8;            // b*H + h (same for both rows)
    const int b    = bh / NHEAD;
    const int q0   = r0 & (SEQ - 1);
    const int q1   = q0 + 1;

    const int tid  = threadIdx.x;        // 0..127
    const int lane = tid & 31;
    const int warp = tid >> 5;           // 0..3
    const int sub  = lane & 15;          // d/4 slot
    const int half = lane >> 4;          // which of 2 k-rows

    __shared__ float sh_scores[2][SEQ];  // scores, then e[k], per row
    __shared__ float sh_red[2][4][DIM];
    __shared__ float sh_max[2][4];
    __shared__ float sh_sum[2][4];
    __shared__ float sh_q[2][DIM];

    // ---- load both q rows ----
    if (tid < 2 * DIM) sh_q[tid >> 6][tid & 63] = q_[(size_t)r0 * DIM + tid];
    __syncthreads();
    const float4 qv0 = *(const float4*)(&sh_q[0][sub * 4]);
    const float4 qv1 = *(const float4*)(&sh_q[1][sub * 4]);

    // ---- Phase B: base scores vs key (L2-hot, loaded ONCE for both rows) ----
    // Same thread writes and later accumulates sh_scores[.][k]: no barrier
    // needed between phases B and C.
    {
        const float* krow = k_ + ((size_t)bh * SEQ + warp * 64 + half) * DIM + sub * 4;
        #pragma unroll 8
        for (int i = 0; i < 32; ++i) {
            const int k = warp * 64 + i * 2 + half;
            float4 c = *(const float4*)(krow + (size_t)i * 2 * DIM);
            float s0 = c.x * qv0.x + c.y * qv0.y + c.z * qv0.z + c.w * qv0.w;
            float s1 = c.x * qv1.x + c.y * qv1.y + c.z * qv1.z + c.w * qv1.w;
            #pragma unroll
            for (int off = 8; off >= 1; off >>= 1) {
                s0 += __shfl_xor_sync(0xffffffffu, s0, off);
                s1 += __shfl_xor_sync(0xffffffffu, s1, off);
            }
            if (sub == 0) {
                sh_scores[0][k] = s0;
                sh_scores[1][k] = s1;
            }
        }
    }

    // ---- Phase C: ks DRAM streams (one slice per row), accumulate ----
    {
        const float* ks0 = ks_ + ((size_t)r0 * SEQ + warp * 64 + half) * DIM + sub * 4;
        const float* ks1 = ks_ + ((size_t)r1 * SEQ + warp * 64 + half) * DIM + sub * 4;
        #pragma unroll 4
        for (int i = 0; i < 32; ++i) {
            const int k = warp * 64 + i * 2 + half;
            float4 a0 = __ldcs((const float4*)(ks0 + (size_t)i * 2 * DIM));
            float4 a1 = __ldcs((const float4*)(ks1 + (size_t)i * 2 * DIM));
            float s0 = a0.x * qv0.x + a0.y * qv0.y + a0.z * qv0.z + a0.w * qv0.w;
            float s1 = a1.x * qv1.x + a1.y * qv1.y + a1.z * qv1.z + a1.w * qv1.w;
            #pragma unroll
            for (int off = 8; off >= 1; off >>= 1) {
                s0 += __shfl_xor_sync(0xffffffffu, s0, off);
                s1 += __shfl_xor_sync(0xffffffffu, s1, off);
            }
            if (sub == 0) {
                sh_scores[0][k] += s0;
                sh_scores[1][k] += s1;
            }
        }
    }
    __syncthreads();

    // ---- softmax per row (2 scores/thread/row) ----
    // mask indexed by q (faithful to reference broadcast [B,1,Sq,1]).
    const float mv0 = (1.0f - mask_[b * SEQ + q0]) * -100000.0f;
    const float mv1 = (1.0f - mask_[b * SEQ + q1]) * -100000.0f;
    float sa0 = (sh_scores[0][tid]       + mv0) * 0.125f;   // 1/sqrt(64)
    float sa1 = (sh_scores[0][tid + 128] + mv0) * 0.125f;
    float sb0 = (sh_scores[1][tid]       + mv1) * 0.125f;
    float sb1 = (sh_scores[1][tid + 128] + mv1) * 0.125f;

    float ma = fmaxf(sa0, sa1);
    float mb = fmaxf(sb0, sb1);
    #pragma unroll
    for (int off = 16; off >= 1; off >>= 1) {
        ma = fmaxf(ma, __shfl_xor_sync(0xffffffffu, ma, off));
        mb = fmaxf(mb, __shfl_xor_sync(0xffffffffu, mb, off));
    }
    if (lane == 0) { sh_max[0][warp] = ma; sh_max[1][warp] = mb; }
    __syncthreads();
    const float max0 = fmaxf(fmaxf(sh_max[0][0], sh_max[0][1]),
                             fmaxf(sh_max[0][2], sh_max[0][3]));
    const float max1 = fmaxf(fmaxf(sh_max[1][0], sh_max[1][1]),
                             fmaxf(sh_max[1][2], sh_max[1][3]));

    const float ea0 = __expf(sa0 - max0);
    const float ea1 = __expf(sa1 - max0);
    const float eb0 = __expf(sb0 - max1);
    const float eb1 = __expf(sb1 - max1);

    // publish e[k] and warp sum partials under ONE barrier
    sh_scores[0][tid]       = ea0;
    sh_scores[0][tid + 128] = ea1;
    sh_scores[1][tid]       = eb0;
    sh_scores[1][tid + 128] = eb1;
    float su0 = ea0 + ea1;
    float su1 = eb0 + eb1;
    #pragma unroll
    for (int off = 16; off >= 1; off >>= 1) {
        su0 += __shfl_xor_sync(0xffffffffu, su0, off);
        su1 += __shfl_xor_sync(0xffffffffu, su1, off);
    }
    if (lane == 0) { sh_sum[0][warp] = su0; sh_sum[1][warp] = su1; }
    __syncthreads();

    const float inv0 = 1.0f / (sh_sum[0][0] + sh_sum[0][1] + sh_sum[0][2] + sh_sum[0][3]);
    const float inv1 = 1.0f / (sh_sum[1][0] + sh_sum[1][1] + sh_sum[1][2] + sh_sum[1][3]);

    // attn outputs straight from registers (coalesced, evict-first)
    __stcs(attn_ + (size_t)r0 * SEQ + tid,       ea0 * inv0);
    __stcs(attn_ + (size_t)r0 * SEQ + tid + 128, ea1 * inv0);
    __stcs(attn_ + (size_t)r1 * SEQ + tid,       eb0 * inv1);
    __stcs(attn_ + (size_t)r1 * SEQ + tid + 128, eb1 * inv1);

    // ---- Pass 2 ----
    float4 acc0 = make_float4(0.0f, 0.0f, 0.0f, 0.0f);
    float4 acc1 = make_float4(0.0f, 0.0f, 0.0f, 0.0f);

    // Phase E: val (L2-hot, loaded ONCE for both rows)
    {
        const float* vbase = v_ + ((size_t)bh * SEQ + warp * 64 + half) * DIM + sub * 4;
        #pragma unroll 8
        for (int i = 0; i < 32; ++i) {
            const int k = warp * 64 + i * 2 + half;
            const float a0 = sh_scores[0][k];
            const float a1 = sh_scores[1][k];
            float4 vv = *(const float4*)(vbase + (size_t)i * 2 * DIM);
            acc0.x = fmaf(a0, vv.x, acc0.x); acc0.y = fmaf(a0, vv.y, acc0.y);
            acc0.z = fmaf(a0, vv.z, acc0.z); acc0.w = fmaf(a0, vv.w, acc0.w);
            acc1.x = fmaf(a1, vv.x, acc1.x); acc1.y = fmaf(a1, vv.y, acc1.y);
            acc1.z = fmaf(a1, vv.z, acc1.z); acc1.w = fmaf(a1, vv.w, acc1.w);
        }
    }

    // Phase F: vs DRAM streams (one slice per row)
    {
        const float* vs0 = vs_ + ((size_t)r0 * SEQ + warp * 64 + half) * DIM + sub * 4;
        const float* vs1 = vs_ + ((size_t)r1 * SEQ + warp * 64 + half) * DIM + sub * 4;
        #pragma unroll 4
        for (int i = 0; i < 32; ++i) {
            const int k = warp * 64 + i * 2 + half;
            const float a0 = sh_scores[0][k];
            const float a1 = sh_scores[1][k];
            float4 s0 = __ldcs((const float4*)(vs0 + (size_t)i * 2 * DIM));
            float4 s1 = __ldcs((const float4*)(vs1 + (size_t)i * 2 * DIM));
            acc0.x = fmaf(a0, s0.x, acc0.x); acc0.y = fmaf(a0, s0.y, acc0.y);
            acc0.z = fmaf(a0, s0.z, acc0.z); acc0.w = fmaf(a0, s0.w, acc0.w);
            acc1.x = fmaf(a1, s1.x, acc1.x); acc1.y = fmaf(a1, s1.y, acc1.y);
            acc1.z = fmaf(a1, s1.z, acc1.z); acc1.w = fmaf(a1, s1.w, acc1.w);
        }
    }

    // fold the two k-halves (lanes sub and sub+16 share d-range)
    #pragma unroll
    {
        acc0.x += __shfl_xor_sync(0xffffffffu, acc0.x, 16);
        acc0.y += __shfl_xor_sync(0xffffffffu, acc0.y, 16);
        acc0.z += __shfl_xor_sync(0xffffffffu, acc0.z, 16);
        acc0.w += __shfl_xor_sync(0xffffffffu, acc0.w, 16);
        acc1.x += __shfl_xor_sync(0xffffffffu, acc1.x, 16);
        acc1.y += __shfl_xor_sync(0xffffffffu, acc1.y, 16);
        acc1.z += __shfl_xor_sync(0xffffffffu, acc1.z, 16);
        acc1.w += __shfl_xor_sync(0xffffffffu, acc1.w, 16);
    }
    if (half == 0) {
        acc0.x *= inv0; acc0.y *= inv0; acc0.z *= inv0; acc0.w *= inv0;
        acc1.x *= inv1; acc1.y *= inv1; acc1.z *= inv1; acc1.w *= inv1;
        *(float4*)(&sh_red[0][warp][sub * 4]) = acc0;
        *(float4*)(&sh_red[1][warp][sub * 4]) = acc1;
    }
    __syncthreads();

    if (tid < 2 * DIM) {
        const int r = tid >> 6;          // 0 or 1
        const int d = tid & 63;
        float v = sh_red[r][0][d] + sh_red[r][1][d]
                + sh_red[r][2][d] + sh_red[r][3][d];
        __stcs(out_ + (size_t)(r0 + r) * DIM + d, v);
    }
}

extern "C" void kernel_launch(void* const* d_in, const int* in_sizes, int n_in,
                              void* d_out, int out_size) {
    const float* q    = (const float*)d_in[0];
    const float* k    = (const float*)d_in[1];
    const float* v    = (const float*)d_in[2];
    const float* ks   = (const float*)d_in[3];
    const float* vs   = (const float*)d_in[4];
    const float* mask = (const float*)d_in[5];

    float* out  = (float*)d_out;                              // [B,H,S,D]
    float* attn = out + (size_t)BATCH * NHEAD * SEQ * DIM;    // [B,H,S,S]

    attn_struct_kernel<<<NROWS / 2, 128>>>(q, k, v, ks, vs, mask, out, attn);
}